// round 5
// baseline (speedup 1.0000x reference)
#include <cuda_runtime.h>
#include <cstdint>

#define BB 256
#define SS 2048
#define FF 64
#define KD 320   // ORDER * FF

// per-(b,f) mean of observed entries — scratch (no allocation allowed)
__device__ __align__(256) float g_mean[BB * FF];

// ---------------------------------------------------------------------------
// Pre-pass: mean[b,f] = sum_s x*mask / (sum_s mask + 1e-8)
// ---------------------------------------------------------------------------
__global__ __launch_bounds__(256) void mean_kernel(const float* __restrict__ x,
                                                   const int* __restrict__ mask) {
    int b = blockIdx.x;
    int f = threadIdx.x & 63;
    int c = threadIdx.x >> 6;          // 4 chunks of 512 steps
    const float* xb = x    + (size_t)b * SS * FF;
    const int*   mb = mask + (size_t)b * SS * FF;

    float sum = 0.f;
    int   cnt = 0;
    int s0 = c * (SS / 4), s1 = s0 + (SS / 4);
    for (int s = s0; s < s1; s++) {
        int idx = s * FF + f;
        int m = mb[idx];
        float xv = xb[idx];
        if (m) { sum += xv; cnt++; }
    }

    __shared__ float ssum[4][64];
    __shared__ int   scnt[4][64];
    ssum[c][f] = sum;
    scnt[c][f] = cnt;
    __syncthreads();
    if (threadIdx.x < 64) {
        float s4 = ssum[0][f] + ssum[1][f] + ssum[2][f] + ssum[3][f];
        int   c4 = scnt[0][f] + scnt[1][f] + scnt[2][f] + scnt[3][f];
        g_mean[b * FF + f] = s4 / ((float)c4 + 1e-8f);
    }
}

// ---------------------------------------------------------------------------
// f32x2 helpers
// ---------------------------------------------------------------------------
__device__ __forceinline__ uint64_t pack2(float a, float b) {
    uint64_t r; asm("mov.b64 %0,{%1,%2};" : "=l"(r) : "f"(a), "f"(b)); return r;
}
__device__ __forceinline__ void fma2(uint64_t& acc, uint64_t a, uint64_t b) {
    asm("fma.rn.f32x2 %0, %1, %2, %0;" : "+l"(acc) : "l"(a), "l"(b));
}
__device__ __forceinline__ float hadd2(uint64_t v) {
    float lo, hi; asm("mov.b64 {%0,%1}, %2;" : "=f"(lo), "=f"(hi) : "l"(v));
    return lo + hi;
}

// ---------------------------------------------------------------------------
// Main recurrence. Grid = 128 CTAs x 256 threads; each CTA advances TWO
// batches in lockstep, and EACH THREAD carries both batches (two independent
// instruction streams sharing one register-resident W slice -> latency of
// one stream is filled by FFMA2s of the other).
// Thread = (fg, q): fg in [0,32) = group of 2 contiguous output features,
// q in [0,8) = K-octant (8 floats/frame). W = 80 floats/thread (40 f32x2).
// Window register-cached per batch as 5 circular 8-float frame slices; only
// the newest frame is re-read from smem each step. One barrier per step.
// Tail: 2045 = 5*409 + peeled 3-phase epilogue (no mid-loop return).
// ---------------------------------------------------------------------------
__global__ __launch_bounds__(256, 1) void var_kernel(
    const float* __restrict__ x, const int* __restrict__ mask,
    const float* __restrict__ W, const float* __restrict__ bias,
    float* __restrict__ out)
{
    int tid = threadIdx.x;
    int fg  = tid >> 3;     // 0..31 feature pair
    int q   = tid & 7;      // 0..7  K-octant
    int f0  = fg << 1;      // first feature of the pair
    int ko  = q << 3;       // first K element of the octant

    __shared__ __align__(16) float win[2][5][FF];   // per-batch circular frames

    // W registers: w[g][frame-row j][pair]  (g in {0,1})
    uint64_t w[2][5][4];
    #pragma unroll
    for (int g = 0; g < 2; g++) {
        #pragma unroll
        for (int j = 0; j < 5; j++) {
            const float4* p4 = (const float4*)(W + (size_t)(f0 + g) * KD + j * FF + ko);
            float4 a = p4[0], c = p4[1];
            w[g][j][0] = pack2(a.x, a.y); w[g][j][1] = pack2(a.z, a.w);
            w[g][j][2] = pack2(c.x, c.y); w[g][j][3] = pack2(c.z, c.w);
        }
    }
    float2 bias2 = *(const float2*)(bias + f0);

    int b0 = blockIdx.x * 2;       // batches b0, b0+1

    // smem window init: per-feature means (both batches)
    for (int i = tid; i < 2 * 5 * FF; i += 256) {
        int h = i / (5 * FF);
        (&win[h][0][0])[i - h * 5 * FF] = g_mean[(b0 + h) * FF + (i & 63)];
    }

    // register window caches: all 5 slots = mean slice
    uint64_t wr[2][5][4];
    #pragma unroll
    for (int h = 0; h < 2; h++) {
        const float4* mp = (const float4*)(g_mean + (b0 + h) * FF + ko);
        float4 a = mp[0], c = mp[1];
        #pragma unroll
        for (int j = 0; j < 5; j++) {
            wr[h][j][0] = pack2(a.x, a.y); wr[h][j][1] = pack2(a.z, a.w);
            wr[h][j][2] = pack2(c.x, c.y); wr[h][j][3] = pack2(c.z, c.w);
        }
    }

    const float2* xb[2]; const int2* mb[2]; float2* ob[2];
    float2 xv[2]; int2 mv[2];
    #pragma unroll
    for (int h = 0; h < 2; h++) {
        xb[h] = (const float2*)(x    + (size_t)(b0 + h) * SS * FF);
        mb[h] = (const int2*)  (mask + (size_t)(b0 + h) * SS * FF);
        ob[h] = (float2*)      (out  + (size_t)(b0 + h) * SS * FF);
        xv[h] = xb[h][fg];          // prefetch step 0 (broadcast over q-lanes)
        mv[h] = mb[h][fg];
    }

    __syncthreads();

    int t = 0;

    // One recurrence step (both batches) at static phase P. Advances t by 1.
    #define STEP(P)                                                            \
    do {                                                                       \
        /* refresh: slot (P+4)%5 holds the newest frame */                     \
        _Pragma("unroll")                                                      \
        for (int h = 0; h < 2; h++) {                                          \
            const float4* nf = (const float4*)(&win[h][(P + 4) % 5][ko]);      \
            float4 a = nf[0], c = nf[1];                                       \
            wr[h][(P + 4) % 5][0] = pack2(a.x, a.y);                           \
            wr[h][(P + 4) % 5][1] = pack2(a.z, a.w);                           \
            wr[h][(P + 4) % 5][2] = pack2(c.x, c.y);                           \
            wr[h][(P + 4) % 5][3] = pack2(c.z, c.w);                           \
        }                                                                      \
        uint64_t acc[2][2] = {{0, 0}, {0, 0}};                                 \
        _Pragma("unroll")                                                      \
        for (int s = 0; s < 5; s++) {                                          \
            const int jp = (s - (P) + 5) % 5;                                  \
            _Pragma("unroll")                                                  \
            for (int o = 0; o < 4; o++) {                                      \
                fma2(acc[0][0], w[0][jp][o], wr[0][s][o]);                     \
                fma2(acc[1][0], w[0][jp][o], wr[1][s][o]);                     \
                fma2(acc[0][1], w[1][jp][o], wr[0][s][o]);                     \
                fma2(acc[1][1], w[1][jp][o], wr[1][s][o]);                     \
            }                                                                  \
        }                                                                      \
        float r00 = hadd2(acc[0][0]), r01 = hadd2(acc[0][1]);                  \
        float r10 = hadd2(acc[1][0]), r11 = hadd2(acc[1][1]);                  \
        _Pragma("unroll")                                                      \
        for (int d = 1; d < 8; d <<= 1) {                                      \
            r00 += __shfl_xor_sync(0xffffffffu, r00, d);                       \
            r01 += __shfl_xor_sync(0xffffffffu, r01, d);                       \
            r10 += __shfl_xor_sync(0xffffffffu, r10, d);                       \
            r11 += __shfl_xor_sync(0xffffffffu, r11, d);                       \
        }                                                                      \
        float2 nv0, nv1;                                                       \
        nv0.x = mv[0].x ? xv[0].x : (r00 + bias2.x);                           \
        nv0.y = mv[0].y ? xv[0].y : (r01 + bias2.y);                           \
        nv1.x = mv[1].x ? xv[1].x : (r10 + bias2.x);                           \
        nv1.y = mv[1].y ? xv[1].y : (r11 + bias2.y);                           \
        if (q == 0) {                                                          \
            *(float2*)(&win[0][(P)][f0]) = nv0;   /* oldest slot <- newest */  \
            *(float2*)(&win[1][(P)][f0]) = nv1;                                \
            ob[0][(size_t)t * 32 + fg] = nv0;                                  \
            ob[1][(size_t)t * 32 + fg] = nv1;                                  \
        }                                                                      \
        if (t + 1 < SS) {                                                      \
            xv[0] = xb[0][(size_t)(t + 1) * 32 + fg];                          \
            mv[0] = mb[0][(size_t)(t + 1) * 32 + fg];                          \
            xv[1] = xb[1][(size_t)(t + 1) * 32 + fg];                          \
            mv[1] = mb[1][(size_t)(t + 1) * 32 + fg];                          \
        }                                                                      \
        __syncthreads();                                                       \
        t++;                                                                   \
    } while (0)

    // 409 * 5 = 2045 steps
    for (int it = 0; it < 409; it++) {
        STEP(0); STEP(1); STEP(2); STEP(3); STEP(4);
    }
    // epilogue: t = 2045, 2046, 2047 (phases 0,1,2 since 2045 % 5 == 0)
    STEP(0); STEP(1); STEP(2);

    #undef STEP
}

// ---------------------------------------------------------------------------
extern "C" void kernel_launch(void* const* d_in, const int* in_sizes, int n_in,
                              void* d_out, int out_size) {
    const float* x    = (const float*)d_in[0];
    const int*   mask = (const int*)  d_in[1];
    const float* W    = (const float*)d_in[2];
    const float* bias = (const float*)d_in[3];
    float*       out  = (float*)d_out;

    mean_kernel<<<BB, 256>>>(x, mask);
    var_kernel<<<BB / 2, 256>>>(x, mask, W, bias, out);
}

// round 6
// speedup vs baseline: 1.2538x; 1.2538x over previous
#include <cuda_runtime.h>
#include <cstdint>

#define BB 256
#define SS 2048
#define FF 64
#define KD 320   // ORDER * FF

// per-(b,f) mean of observed entries — scratch (no allocation allowed)
__device__ __align__(256) float g_mean[BB * FF];

// ---------------------------------------------------------------------------
// Pre-pass: mean[b,f] = sum_s x*mask / (sum_s mask + 1e-8)
// ---------------------------------------------------------------------------
__global__ __launch_bounds__(256) void mean_kernel(const float* __restrict__ x,
                                                   const int* __restrict__ mask) {
    int b = blockIdx.x;
    int f = threadIdx.x & 63;
    int c = threadIdx.x >> 6;          // 4 chunks of 512 steps
    const float* xb = x    + (size_t)b * SS * FF;
    const int*   mb = mask + (size_t)b * SS * FF;

    float sum = 0.f;
    int   cnt = 0;
    int s0 = c * (SS / 4), s1 = s0 + (SS / 4);
    for (int s = s0; s < s1; s++) {
        int idx = s * FF + f;
        int m = mb[idx];
        float xv = xb[idx];
        if (m) { sum += xv; cnt++; }
    }

    __shared__ float ssum[4][64];
    __shared__ int   scnt[4][64];
    ssum[c][f] = sum;
    scnt[c][f] = cnt;
    __syncthreads();
    if (threadIdx.x < 64) {
        float s4 = ssum[0][f] + ssum[1][f] + ssum[2][f] + ssum[3][f];
        int   c4 = scnt[0][f] + scnt[1][f] + scnt[2][f] + scnt[3][f];
        g_mean[b * FF + f] = s4 / ((float)c4 + 1e-8f);
    }
}

// ---------------------------------------------------------------------------
// f32x2 helpers
// ---------------------------------------------------------------------------
__device__ __forceinline__ uint64_t pack2(float a, float b) {
    uint64_t r; asm("mov.b64 %0,{%1,%2};" : "=l"(r) : "f"(a), "f"(b)); return r;
}
__device__ __forceinline__ void fma2(uint64_t& acc, uint64_t a, uint64_t b) {
    asm("fma.rn.f32x2 %0, %1, %2, %0;" : "+l"(acc) : "l"(a), "l"(b));
}
__device__ __forceinline__ float hadd2(uint64_t v) {
    float lo, hi; asm("mov.b64 {%0,%1}, %2;" : "=f"(lo), "=f"(hi) : "l"(v));
    return lo + hi;
}

// ---------------------------------------------------------------------------
// Main recurrence. One CTA (128 threads) per batch, 256 CTAs, 2 CTAs/SM.
// Thread = (fg, q): fg = group of 4 contiguous output features, q = K-octant.
// W register-resident (80 f32x2/thread); window register-cached as 5 circular
// 8-float frame slices; only the newest frame is re-read from smem each step.
//
// SOFTWARE PIPELINE: at phase P the refreshed slot sN=(P+4)%5 always carries
// W-row 4; the other 4 slots (rows 0..3) are unchanged from the previous
// step. Their 64 FFMA2 ("partial") are computed at the END of the previous
// step, before the barrier. The post-barrier critical path is only:
// LDS(new frame) -> 4-deep FFMA2 -> hadd -> 3-level shfl -> select -> STS.
// ---------------------------------------------------------------------------
__global__ __launch_bounds__(128, 2) void var_kernel(
    const float* __restrict__ x, const int* __restrict__ mask,
    const float* __restrict__ W, const float* __restrict__ bias,
    float* __restrict__ out)
{
    int tid = threadIdx.x;
    int b   = blockIdx.x;
    int fg  = tid >> 3;     // 0..15 feature group
    int q   = tid & 7;      // 0..7  K-octant
    int f0  = fg << 2;
    int ko  = q << 3;

    __shared__ __align__(16) float win[5][FF];   // circular frame buffer

    // W registers: w[g][frame-row j][pair]
    uint64_t w[4][5][4];
    #pragma unroll
    for (int g = 0; g < 4; g++) {
        #pragma unroll
        for (int j = 0; j < 5; j++) {
            const float4* p4 = (const float4*)(W + (size_t)(f0 + g) * KD + j * FF + ko);
            float4 a = p4[0], c = p4[1];
            w[g][j][0] = pack2(a.x, a.y); w[g][j][1] = pack2(a.z, a.w);
            w[g][j][2] = pack2(c.x, c.y); w[g][j][3] = pack2(c.z, c.w);
        }
    }
    float4 bias4 = *(const float4*)(bias + f0);

    // smem window init: per-feature means
    for (int i = tid; i < 5 * FF; i += 128)
        (&win[0][0])[i] = g_mean[b * FF + (i & 63)];

    // register window cache: all 5 slots = mean slice
    uint64_t wr[5][4];
    {
        const float4* mp = (const float4*)(g_mean + b * FF + ko);
        float4 a = mp[0], c = mp[1];
        #pragma unroll
        for (int j = 0; j < 5; j++) {
            wr[j][0] = pack2(a.x, a.y); wr[j][1] = pack2(a.z, a.w);
            wr[j][2] = pack2(c.x, c.y); wr[j][3] = pack2(c.z, c.w);
        }
    }

    const float4* xb = (const float4*)(x    + (size_t)b * SS * FF);
    const int4*   mb = (const int4*)  (mask + (size_t)b * SS * FF);
    float4*       ob = (float4*)      (out  + (size_t)b * SS * FF);

    // Prefetch step 0 (8 q-lanes load the same float4 — broadcast)
    float4 xv = xb[fg];
    int4   mv = mb[fg];

    // Bootstrap partial for phase 0: slots s=0..3 carry rows 0..3.
    uint64_t part0 = 0, part1 = 0, part2 = 0, part3 = 0;
    #pragma unroll
    for (int s = 0; s < 4; s++) {
        #pragma unroll
        for (int o = 0; o < 4; o++) {
            fma2(part0, w[0][s][o], wr[s][o]);
            fma2(part1, w[1][s][o], wr[s][o]);
            fma2(part2, w[2][s][o], wr[s][o]);
            fma2(part3, w[3][s][o], wr[s][o]);
        }
    }

    __syncthreads();

    int t = 0;

    // One recurrence step at static phase P. Advances t by 1.
    #define STEP(P)                                                            \
    do {                                                                       \
        /* critical path: refresh slot sN=(P+4)%5 (always W-row 4) */          \
        {                                                                      \
            const float4* nf = (const float4*)(&win[(P + 4) % 5][ko]);         \
            float4 a = nf[0], c = nf[1];                                       \
            wr[(P + 4) % 5][0] = pack2(a.x, a.y);                              \
            wr[(P + 4) % 5][1] = pack2(a.z, a.w);                              \
            wr[(P + 4) % 5][2] = pack2(c.x, c.y);                              \
            wr[(P + 4) % 5][3] = pack2(c.z, c.w);                              \
        }                                                                      \
        uint64_t acc0 = part0, acc1 = part1, acc2 = part2, acc3 = part3;       \
        _Pragma("unroll")                                                      \
        for (int o = 0; o < 4; o++) {                                          \
            fma2(acc0, w[0][4][o], wr[(P + 4) % 5][o]);                        \
            fma2(acc1, w[1][4][o], wr[(P + 4) % 5][o]);                        \
            fma2(acc2, w[2][4][o], wr[(P + 4) % 5][o]);                        \
            fma2(acc3, w[3][4][o], wr[(P + 4) % 5][o]);                        \
        }                                                                      \
        float r0 = hadd2(acc0), r1 = hadd2(acc1);                              \
        float r2 = hadd2(acc2), r3 = hadd2(acc3);                              \
        _Pragma("unroll")                                                      \
        for (int d = 1; d < 8; d <<= 1) {                                      \
            r0 += __shfl_xor_sync(0xffffffffu, r0, d);                         \
            r1 += __shfl_xor_sync(0xffffffffu, r1, d);                         \
            r2 += __shfl_xor_sync(0xffffffffu, r2, d);                         \
            r3 += __shfl_xor_sync(0xffffffffu, r3, d);                         \
        }                                                                      \
        float4 nv;                                                             \
        nv.x = mv.x ? xv.x : (r0 + bias4.x);                                   \
        nv.y = mv.y ? xv.y : (r1 + bias4.y);                                   \
        nv.z = mv.z ? xv.z : (r2 + bias4.z);                                   \
        nv.w = mv.w ? xv.w : (r3 + bias4.w);                                   \
        if (q == 0) {                                                          \
            *(float4*)(&win[(P)][f0]) = nv;   /* oldest slot <- newest */      \
            ob[(size_t)t * 16 + fg] = nv;                                      \
        }                                                                      \
        if (t + 1 < SS) {                                                      \
            xv = xb[(size_t)(t + 1) * 16 + fg];                                \
            mv = mb[(size_t)(t + 1) * 16 + fg];                                \
        }                                                                      \
        /* pipeline: partials for step t+1 over the 4 surviving slots.     */  \
        /* At phase P+1, slot s (s != P) carries row (s-P-1+5)%5 in 0..3.  */  \
        part0 = 0; part1 = 0; part2 = 0; part3 = 0;                            \
        _Pragma("unroll")                                                      \
        for (int s = 0; s < 5; s++) {                                          \
            if (s != (P)) {                                                    \
                const int jp = (s - (P) - 1 + 5) % 5;                          \
                _Pragma("unroll")                                              \
                for (int o = 0; o < 4; o++) {                                  \
                    fma2(part0, w[0][jp][o], wr[s][o]);                        \
                    fma2(part1, w[1][jp][o], wr[s][o]);                        \
                    fma2(part2, w[2][jp][o], wr[s][o]);                        \
                    fma2(part3, w[3][jp][o], wr[s][o]);                        \
                }                                                              \
            }                                                                  \
        }                                                                      \
        __syncthreads();                                                       \
        t++;                                                                   \
    } while (0)

    // 409 * 5 = 2045 steps
    for (int it = 0; it < 409; it++) {
        STEP(0); STEP(1); STEP(2); STEP(3); STEP(4);
    }
    // epilogue: t = 2045, 2046, 2047 (phases 0,1,2 since 2045 % 5 == 0)
    STEP(0); STEP(1); STEP(2);

    #undef STEP
}

// ---------------------------------------------------------------------------
extern "C" void kernel_launch(void* const* d_in, const int* in_sizes, int n_in,
                              void* d_out, int out_size) {
    const float* x    = (const float*)d_in[0];
    const int*   mask = (const int*)  d_in[1];
    const float* W    = (const float*)d_in[2];
    const float* bias = (const float*)d_in[3];
    float*       out  = (float*)d_out;

    mean_kernel<<<BB, 256>>>(x, mask);
    var_kernel<<<BB, 128>>>(x, mask, W, bias, out);
}